// round 12
// baseline (speedup 1.0000x reference)
#include <cuda_runtime.h>
#include <cuda_fp16.h>

#define BB 256
#define DD 564
#define SS 40
#define PP 20
#define NBL 6
#define NCOL 2256      /* 4*DD */
#define ROWS 10240     /* BB*SS */
#define OUTIN 1128
#define KP 288         /* padded k-pairs (576/2) */
#define NIT 36         /* scan k-iterations of 8 kp */
#define NKCW 18        /* wgemm k-chunks of 16 kp */
#define CBLK 36
#define BBLK 4

// ---------------- scratch (static device globals; no allocation) ----------------
__device__ float g_x[ROWS * DD];           // activations (b,s,d)
__device__ float g_pre[SS * BB * NCOL];    // (s,b, e*4+g)  gate-interleaved
__device__ float g_mean[DD];
__device__ float g_rstd[DD];
__device__ unsigned g_bcnt[BBLK * 32];
__device__ unsigned g_bgen[BBLK * 32];
// fp16-split packed operands: uint2 = {hi2 (k,k+1), lo2 (k,k+1)}
__device__ uint2 g_h16[ROWS * KP];         // layernorm out
__device__ uint2 g_W16[4 * KP * DD];       // W  [g][kp][e]
__device__ uint2 g_R16[KP * NCOL];         // R  [kp][e*4+g]
__device__ uint2 g_h16s[2][BB * KP];       // scan hidden state, split+packed, dbl-buf

// ---------------- fp16 split helpers ----------------
__device__ __forceinline__ uint2 pack_split(float x0, float x1) {
    __half h0 = __float2half_rn(x0), h1 = __float2half_rn(x1);
    __half l0 = __float2half_rn(x0 - __half2float(h0));
    __half l1 = __float2half_rn(x1 - __half2float(h1));
    uint2 r;
    r.x = (unsigned)__half_as_ushort(h0) | ((unsigned)__half_as_ushort(h1) << 16);
    r.y = (unsigned)__half_as_ushort(l0) | ((unsigned)__half_as_ushort(l1) << 16);
    return r;
}
__device__ __forceinline__ void mma16(float* d, const unsigned* a, const unsigned* b) {
    asm volatile(
        "mma.sync.aligned.m16n8k16.row.col.f32.f16.f16.f32 "
        "{%0,%1,%2,%3}, {%4,%5,%6,%7}, {%8,%9}, {%0,%1,%2,%3};"
        : "+f"(d[0]), "+f"(d[1]), "+f"(d[2]), "+f"(d[3])
        : "r"(a[0]), "r"(a[1]), "r"(a[2]), "r"(a[3]), "r"(b[0]), "r"(b[1]));
}

// ---------------- input reshape ----------------
__global__ void k_reshape(const float* __restrict__ inp) {
    int idx = blockIdx.x * blockDim.x + threadIdx.x;
    if (idx >= ROWS * DD) return;
    int d = idx % DD;
    int r = idx / DD;
    int s = r % SS;
    int b = r / SS;
    g_x[idx] = inp[(size_t)b * (DD * SS) + d * SS + s];
}

// ---------------- weight conversion (per layer) ----------------
__global__ void k_convW(const float* __restrict__ W) {
    int idx = blockIdx.x * blockDim.x + threadIdx.x;
    if (idx >= 4 * KP * DD) return;
    int g = idx / (KP * DD);
    int rem = idx - g * KP * DD;
    int kp = rem / DD;
    int e  = rem - kp * DD;
    int d0 = kp * 2, d1 = d0 + 1;
    float x0 = (d0 < DD) ? W[(size_t)g * DD * DD + (size_t)d0 * DD + e] : 0.f;
    float x1 = (d1 < DD) ? W[(size_t)g * DD * DD + (size_t)d1 * DD + e] : 0.f;
    g_W16[idx] = pack_split(x0, x1);
}
__global__ void k_convR(const float* __restrict__ R) {
    int idx = blockIdx.x * blockDim.x + threadIdx.x;
    if (idx >= KP * NCOL) return;
    int kp  = idx / NCOL;
    int col = idx - kp * NCOL;
    int e = col >> 2, g = col & 3;
    int d0 = kp * 2, d1 = d0 + 1;
    float x0 = (d0 < DD) ? R[(size_t)g * DD * DD + (size_t)d0 * DD + e] : 0.f;
    float x1 = (d1 < DD) ? R[(size_t)g * DD * DD + (size_t)d1 * DD + e] : 0.f;
    g_R16[idx] = pack_split(x0, x1);
}

// ---------------- layernorm: emits split/packed h ----------------
__global__ void k_layernorm(const float* __restrict__ lng, const float* __restrict__ lnb) {
    int row = blockIdx.x;
    const float* xr = g_x + (size_t)row * DD;
    __shared__ float red[128];
    __shared__ float s_mu, s_rs;
    float s1 = 0.f, s2 = 0.f;
    for (int d = threadIdx.x; d < DD; d += 128) { float v = xr[d]; s1 += v; s2 += v * v; }
    red[threadIdx.x] = s1; __syncthreads();
    for (int o = 64; o > 0; o >>= 1) { if (threadIdx.x < o) red[threadIdx.x] += red[threadIdx.x + o]; __syncthreads(); }
    if (threadIdx.x == 0) s_mu = red[0] / DD;
    __syncthreads();
    red[threadIdx.x] = s2; __syncthreads();
    for (int o = 64; o > 0; o >>= 1) { if (threadIdx.x < o) red[threadIdx.x] += red[threadIdx.x + o]; __syncthreads(); }
    if (threadIdx.x == 0) {
        float var = red[0] / DD - s_mu * s_mu;
        s_rs = rsqrtf(var + 1e-5f);
    }
    __syncthreads();
    float mu = s_mu, rs = s_rs;
    for (int kp = threadIdx.x; kp < KP; kp += 128) {
        int d0 = kp * 2, d1 = d0 + 1;
        float x0 = (d0 < DD) ? (xr[d0] - mu) * rs * lng[d0] + lnb[d0] : 0.f;
        float x1 = (d1 < DD) ? (xr[d1] - mu) * rs * lng[d1] + lnb[d1] : 0.f;
        g_h16[(size_t)row * KP + kp] = pack_split(x0, x1);
    }
}

// ---------------- W GEMM, fp16 3-split m16n8k16 (unchanged) ----------------
__global__ void __launch_bounds__(128) k_wgemm(const float* __restrict__ bias) {
    __shared__ uint2 sA[64 * 20];   // [row][kp0..15], stride 20
    __shared__ uint2 sB[16 * 68];   // [kp][e0..63],   stride 68
    int g  = blockIdx.z;
    int n0 = blockIdx.x * 64;
    int m0 = blockIdx.y * 64;
    int t = threadIdx.x, lane = t & 31, wid = t >> 5;
    int wm = wid >> 1, wn = wid & 1;

    float acc[2][4][4];
#pragma unroll
    for (int i = 0; i < 2; i++)
#pragma unroll
        for (int j = 0; j < 4; j++)
#pragma unroll
            for (int k = 0; k < 4; k++) acc[i][j][k] = 0.f;

    const uint2* Wbase = g_W16 + (size_t)g * KP * DD;

    for (int kc = 0; kc < NKCW; kc++) {
        {
            int row = t >> 1, kb = (t & 1) * 8;
            const uint2* src = g_h16 + (size_t)(m0 + row) * KP + kc * 16 + kb;
            uint2* dst = sA + row * 20 + kb;
            *(uint4*)(dst)     = *(const uint4*)(src);
            *(uint4*)(dst + 2) = *(const uint4*)(src + 2);
            *(uint4*)(dst + 4) = *(const uint4*)(src + 4);
            *(uint4*)(dst + 6) = *(const uint4*)(src + 6);
        }
        {
#pragma unroll
            for (int it = 0; it < 8; it++) {
                int i = t + it * 128;
                int kpr = i >> 6, c = i & 63;
                int ge = n0 + c;
                uint2 v = make_uint2(0u, 0u);
                if (ge < DD) v = Wbase[(size_t)(kc * 16 + kpr) * DD + ge];
                sB[kpr * 68 + c] = v;
            }
        }
        __syncthreads();
#pragma unroll
        for (int ts = 0; ts < 2; ts++) {
            int kpf = ts * 8 + (lane & 3);
            unsigned ah[2][4], al[2][4];
#pragma unroll
            for (int mi = 0; mi < 2; mi++) {
                int row = wm * 32 + mi * 16 + (lane >> 2);
                const uint2* Ap = sA + row * 20;
                uint2 x0 = Ap[kpf], x1 = Ap[160 + kpf];
                uint2 x2 = Ap[kpf + 4], x3 = Ap[160 + kpf + 4];
                ah[mi][0] = x0.x; ah[mi][1] = x1.x; ah[mi][2] = x2.x; ah[mi][3] = x3.x;
                al[mi][0] = x0.y; al[mi][1] = x1.y; al[mi][2] = x2.y; al[mi][3] = x3.y;
            }
#pragma unroll
            for (int ni = 0; ni < 4; ni++) {
                int cb = wn * 32 + ni * 8 + (lane >> 2);
                uint2 b0 = sB[kpf * 68 + cb];
                uint2 b1 = sB[(kpf + 4) * 68 + cb];
                unsigned bh[2] = {b0.x, b1.x};
                unsigned bl[2] = {b0.y, b1.y};
#pragma unroll
                for (int mi = 0; mi < 2; mi++) {
                    mma16(acc[mi][ni], ah[mi], bh);
                    mma16(acc[mi][ni], ah[mi], bl);
                    mma16(acc[mi][ni], al[mi], bh);
                }
            }
        }
        __syncthreads();
    }
    const float* bp = bias + g * DD;
#pragma unroll
    for (int mi = 0; mi < 2; mi++) {
        int row0 = m0 + wm * 32 + mi * 16 + (lane >> 2);
        int row1 = row0 + 8;
        int b0r = row0 / SS, s0r = row0 - b0r * SS;
        int b1r = row1 / SS, s1r = row1 - b1r * SS;
        float* o0 = g_pre + (size_t)(s0r * BB + b0r) * NCOL + g;
        float* o1 = g_pre + (size_t)(s1r * BB + b1r) * NCOL + g;
#pragma unroll
        for (int ni = 0; ni < 4; ni++) {
            int e = n0 + wn * 32 + ni * 8 + (lane & 3) * 2;
            if (e < DD) {
                float bv0 = bp[e], bv1 = bp[e + 1];
                o0[(e) * 4]     = acc[mi][ni][0] + bv0;
                o0[(e + 1) * 4] = acc[mi][ni][1] + bv1;
                o1[(e) * 4]     = acc[mi][ni][2] + bv0;
                o1[(e + 1) * 4] = acc[mi][ni][3] + bv1;
            }
        }
    }
}

// ---------------- persistent scan ----------------
#define SB_SZ (KP * 68 * 8)            /* 156672: R hi+lo persistent */
#define SCAN_SMEM SB_SZ

__device__ __forceinline__ void group_barrier(int grp, unsigned target) {
    __threadfence();
    __syncthreads();
    if (threadIdx.x == 0) {
        unsigned arr = atomicAdd(&g_bcnt[grp * 32], 1u);
        if (arr == CBLK - 1u) {
            *((volatile unsigned*)&g_bcnt[grp * 32]) = 0u;
            __threadfence();
            atomicExch(&g_bgen[grp * 32], target);
        } else {
            while (*((volatile unsigned*)&g_bgen[grp * 32]) < target) __nanosleep(32);
            __threadfence();
        }
    }
    __syncthreads();
}

__global__ void __launch_bounds__(256, 1) k_scan() {
    extern __shared__ char smraw[];
    uint2* sB = (uint2*)smraw;                 // [kp][c], stride 68

    int t = threadIdx.x, lane = t & 31;
    int wid = t >> 5, wm = wid >> 2, wn = wid & 3;
    int cb0 = blockIdx.x * 64;
    int b0  = blockIdx.y * 64;
    int grp = blockIdx.y;

    // fill persistent R tile (hi+lo)
    for (int i = t; i < KP * 64; i += 256) {
        int kp = i >> 6, c = i & 63;
        int gc = cb0 + c;
        uint2 v = make_uint2(0u, 0u);
        if (gc < NCOL) v = g_R16[(size_t)kp * NCOL + gc];
        sB[kp * 68 + c] = v;
    }

    // zero h0 (split/packed) for this b-group (redundant across col-blocks; benign)
    for (int i = t; i < 64 * KP; i += 256) g_h16s[0][(size_t)b0 * KP + i] = make_uint2(0u, 0u);

    float sc[2][2][2], snr[2][2][2], smx[2][2][2];
#pragma unroll
    for (int a = 0; a < 2; a++)
#pragma unroll
        for (int b = 0; b < 2; b++)
#pragma unroll
            for (int c = 0; c < 2; c++) { sc[a][b][c] = 0.f; snr[a][b][c] = 0.f; smx[a][b][c] = 0.f; }

    unsigned target = *((volatile unsigned*)&g_bgen[grp * 32]);
    ++target; group_barrier(grp, target);

    // A-fragment row bases for this thread (4 rows: mi0 -> r, r+8; mi1 -> r+16, r+24)
    int rA = b0 + wm * 32 + (lane >> 2);
    int kq = lane & 3;

    for (int s = 0; s < SS; s++) {
        const uint2* hb = g_h16s[s & 1];
        const uint2* pr0 = hb + (size_t)(rA)      * KP;
        const uint2* pr1 = hb + (size_t)(rA + 8)  * KP;
        const uint2* pr2 = hb + (size_t)(rA + 16) * KP;
        const uint2* pr3 = hb + (size_t)(rA + 24) * KP;
        uint2* hn16 = g_h16s[(s & 1) ^ 1];

        float acc[2][2][4];
#pragma unroll
        for (int i = 0; i < 2; i++)
#pragma unroll
            for (int j = 0; j < 2; j++)
#pragma unroll
                for (int k = 0; k < 4; k++) acc[i][j][k] = 0.f;

        uint2 Abuf[2][8];
        {   // preload it=0
            int q = kq;
            Abuf[0][0] = __ldcg(pr0 + q);     Abuf[0][1] = __ldcg(pr1 + q);
            Abuf[0][2] = __ldcg(pr0 + q + 4); Abuf[0][3] = __ldcg(pr1 + q + 4);
            Abuf[0][4] = __ldcg(pr2 + q);     Abuf[0][5] = __ldcg(pr3 + q);
            Abuf[0][6] = __ldcg(pr2 + q + 4); Abuf[0][7] = __ldcg(pr3 + q + 4);
        }

#pragma unroll 2
        for (int it = 0; it < NIT; it++) {
            if (it + 1 < NIT) {   // prefetch next iteration's A fragments
                int q = (it + 1) * 8 + kq;
                uint2* d = Abuf[(it + 1) & 1];
                d[0] = __ldcg(pr0 + q);     d[1] = __ldcg(pr1 + q);
                d[2] = __ldcg(pr0 + q + 4); d[3] = __ldcg(pr1 + q + 4);
                d[4] = __ldcg(pr2 + q);     d[5] = __ldcg(pr3 + q);
                d[6] = __ldcg(pr2 + q + 4); d[7] = __ldcg(pr3 + q + 4);
            }
            const uint2* A = Abuf[it & 1];
            unsigned ah[2][4], al[2][4];
#pragma unroll
            for (int mi = 0; mi < 2; mi++) {
                ah[mi][0] = A[mi * 4 + 0].x; ah[mi][1] = A[mi * 4 + 1].x;
                ah[mi][2] = A[mi * 4 + 2].x; ah[mi][3] = A[mi * 4 + 3].x;
                al[mi][0] = A[mi * 4 + 0].y; al[mi][1] = A[mi * 4 + 1].y;
                al[mi][2] = A[mi * 4 + 2].y; al[mi][3] = A[mi * 4 + 3].y;
            }
            int kpf = it * 8 + kq;
            unsigned bh[2][2], bl[2][2];
#pragma unroll
            for (int ni = 0; ni < 2; ni++) {
                int cb = wn * 16 + ni * 8 + (lane >> 2);
                uint2 b0v = sB[kpf * 68 + cb];
                uint2 b1v = sB[(kpf + 4) * 68 + cb];
                bh[ni][0] = b0v.x; bh[ni][1] = b1v.x;
                bl[ni][0] = b0v.y; bl[ni][1] = b1v.y;
            }
            // term-major: 4 independent accs between same-acc reuse
#pragma unroll
            for (int mi = 0; mi < 2; mi++)
#pragma unroll
                for (int ni = 0; ni < 2; ni++) mma16(acc[mi][ni], ah[mi], bh[ni]);
#pragma unroll
            for (int mi = 0; mi < 2; mi++)
#pragma unroll
                for (int ni = 0; ni < 2; ni++) mma16(acc[mi][ni], ah[mi], bl[ni]);
#pragma unroll
            for (int mi = 0; mi < 2; mi++)
#pragma unroll
                for (int ni = 0; ni < 2; ni++) mma16(acc[mi][ni], al[mi], bh[ni]);
        }

        // fused sLSTM epilogue; h_new written back pre-split/packed
#pragma unroll
        for (int mi = 0; mi < 2; mi++) {
            int br = b0 + wm * 32 + mi * 16 + (lane >> 2);
#pragma unroll
            for (int ni = 0; ni < 2; ni++) {
                float d0 = acc[mi][ni][0], d1 = acc[mi][ni][1];
                float d2 = acc[mi][ni][2], d3 = acc[mi][ni][3];
                float p0 = __shfl_xor_sync(0xffffffffu, d0, 1);
                float p1 = __shfl_xor_sync(0xffffffffu, d1, 1);
                float p2 = __shfl_xor_sync(0xffffffffu, d2, 1);
                float p3 = __shfl_xor_sync(0xffffffffu, d3, 1);
                if ((lane & 1) == 0) {
                    int c = cb0 + wn * 16 + ni * 8 + (lane & 3) * 2;
                    bool valid = (c < NCOL);
                    int e = c >> 2;
                    float hvv[2];
#pragma unroll
                    for (int rr = 0; rr < 2; rr++) {
                        int bb = br + rr * 8;
                        float4 pr = make_float4(0.f, 0.f, 0.f, 0.f);
                        if (valid) pr = *(const float4*)(g_pre + (size_t)(s * BB + bb) * NCOL + c);
                        float it = (rr ? d2 : d0) + pr.x;
                        float ft = (rr ? d3 : d1) + pr.y;
                        float zt = (rr ? p2 : p0) + pr.z;
                        float ot = (rr ? p3 : p1) + pr.w;
                        float mo = smx[mi][ni][rr];
                        float mn = fmaxf(ft + mo, it);
                        float iv = expf(it - mn);
                        float fv = expf(ft + mo - mn);
                        float cn = fv * sc[mi][ni][rr] + iv * tanhf(zt);
                        float nn = fv * snr[mi][ni][rr] + iv;
                        float sg = 1.f / (1.f + expf(-ot));
                        float hv = sg * cn / fmaxf(nn, 1e-6f);
                        sc[mi][ni][rr] = cn; snr[mi][ni][rr] = nn; smx[mi][ni][rr] = mn;
                        hvv[rr] = valid ? hv : 0.f;
                        if (valid) g_x[(size_t)(bb * SS + s) * DD + e] += hv;
                    }
                    // pack (e, e+1) pairs: lane with (lane&3)==0 holds e, partner lane^2 holds e+1
                    float o0 = __shfl_xor_sync(0x55555555u, hvv[0], 2);
                    float o1 = __shfl_xor_sync(0x55555555u, hvv[1], 2);
                    if ((lane & 3) == 0) {
                        int kp = c >> 3;    // e/2, e even on these lanes
                        hn16[(size_t)br * KP + kp]       = pack_split(hvv[0], o0);
                        hn16[(size_t)(br + 8) * KP + kp] = pack_split(hvv[1], o1);
                    }
                }
            }
        }
        ++target; group_barrier(grp, target);
    }
}

// ---------------- batchnorm statistics ----------------
__global__ void k_bnstats() {
    int d = blockIdx.x;
    __shared__ float r1[256], r2[256];
    float s1 = 0.f, s2 = 0.f;
    for (int r = threadIdx.x; r < ROWS; r += 256) {
        float v = g_x[(size_t)r * DD + d];
        s1 += v; s2 += v * v;
    }
    r1[threadIdx.x] = s1; r2[threadIdx.x] = s2; __syncthreads();
    for (int o = 128; o > 0; o >>= 1) {
        if (threadIdx.x < o) { r1[threadIdx.x] += r1[threadIdx.x + o]; r2[threadIdx.x] += r2[threadIdx.x + o]; }
        __syncthreads();
    }
    if (threadIdx.x == 0) {
        float mu = r1[0] / (float)ROWS;
        float var = r2[0] / (float)ROWS - mu * mu;
        g_mean[d] = mu;
        g_rstd[d] = rsqrtf(var + 1e-5f);
    }
}

// ---------------- final projection ----------------
__global__ void k_final(const float* __restrict__ w6, const float* __restrict__ b6,
                        const float* __restrict__ bng, const float* __restrict__ bnb,
                        float* __restrict__ out) {
    int bp = blockIdx.x;
    int b = bp / PP, p = bp % PP;
    __shared__ float r0[128], r1[128];
    float a0 = 0.f, a1 = 0.f;
    for (int i = threadIdx.x; i < OUTIN; i += 128) {
        int flat = p * OUTIN + i;
        int d = flat / SS, s = flat % SS;
        float v = g_x[(size_t)(b * SS + s) * DD + d];
        float xn = (v - g_mean[d]) * g_rstd[d] * bng[d] + bnb[d];
        a0 += xn * w6[i * 2 + 0];
        a1 += xn * w6[i * 2 + 1];
    }
    r0[threadIdx.x] = a0; r1[threadIdx.x] = a1; __syncthreads();
    for (int o = 64; o > 0; o >>= 1) {
        if (threadIdx.x < o) { r0[threadIdx.x] += r0[threadIdx.x + o]; r1[threadIdx.x] += r1[threadIdx.x + o]; }
        __syncthreads();
    }
    if (threadIdx.x == 0) {
        out[bp * 2 + 0] = tanhf(r0[0] + b6[0]);
        out[bp * 2 + 1] = tanhf(r1[0] + b6[1]);
    }
}

// ---------------- launch ----------------
extern "C" void kernel_launch(void* const* d_in, const int* in_sizes, int n_in,
                              void* d_out, int out_size) {
    const float* inp = (const float*)d_in[0];
    const float* Wg  = (const float*)d_in[1];
    const float* Rg  = (const float*)d_in[2];
    const float* bgp = (const float*)d_in[3];
    const float* lng = (const float*)d_in[4];
    const float* lnb = (const float*)d_in[5];
    const float* bng = (const float*)d_in[6];
    const float* bnb = (const float*)d_in[7];
    const float* w6  = (const float*)d_in[8];
    const float* b6  = (const float*)d_in[9];
    float* out = (float*)d_out;

    cudaFuncSetAttribute(k_scan, cudaFuncAttributeMaxDynamicSharedMemorySize, SCAN_SMEM);

    const int NWQ = 4 * KP * DD;
    k_reshape<<<(ROWS * DD + 255) / 256, 256>>>(inp);
    for (int l = 0; l < NBL; l++) {
        k_convW<<<(NWQ + 255) / 256, 256>>>(Wg + (size_t)l * 4 * DD * DD);
        k_convR<<<(KP * NCOL + 255) / 256, 256>>>(Rg + (size_t)l * 4 * DD * DD);
        k_layernorm<<<ROWS, 128>>>(lng + l * DD, lnb + l * DD);
        k_wgemm<<<dim3(9, 160, 4), 128>>>(bgp + (size_t)l * 4 * DD);
        k_scan<<<dim3(CBLK, BBLK), 256, SCAN_SMEM>>>();
    }
    k_bnstats<<<DD, 256>>>();
    k_final<<<BB * PP, 128>>>(w6, b6, bng, bnb, out);
}

// round 13
// speedup vs baseline: 1.1405x; 1.1405x over previous
#include <cuda_runtime.h>
#include <cuda_fp16.h>

#define BB 256
#define DD 564
#define DPAD 576
#define SS 40
#define PP 20
#define NBL 6
#define NCOL 2256      /* 4*DD */
#define ROWS 10240     /* BB*SS */
#define OUTIN 1128
#define KP 288         /* padded k-pairs (576/2) */
#define NKC9 9         /* scan k-chunks of 32 kp */
#define NKCW 18        /* wgemm k-chunks of 16 kp */
#define CBLK 36
#define BBLK 4

// ---------------- scratch (static device globals; no allocation) ----------------
__device__ float g_x[ROWS * DD];           // activations (b,s,d)
__device__ float g_pre[SS * BB * NCOL];    // (s,b, e*4+g)  gate-interleaved
__device__ float g_mean[DD];
__device__ float g_rstd[DD];
__device__ unsigned g_bcnt[BBLK * 32];
__device__ unsigned g_bgen[BBLK * 32];
// fp16-split packed operands: uint2 = {hi2 (k,k+1), lo2 (k,k+1)}
__device__ uint2 g_h16[ROWS * KP];         // layernorm out
__device__ uint2 g_W16[4 * KP * DPAD];     // W  [g][kp][e], e padded to 576
__device__ uint2 g_R16[KP * NCOL];         // R  [kp][e*4+g]
__device__ uint2 g_h16s[2][BB * KP];       // scan hidden state, split+packed, dbl-buf

// ---------------- fp16 split helpers ----------------
__device__ __forceinline__ uint2 pack_split(float x0, float x1) {
    __half h0 = __float2half_rn(x0), h1 = __float2half_rn(x1);
    __half l0 = __float2half_rn(x0 - __half2float(h0));
    __half l1 = __float2half_rn(x1 - __half2float(h1));
    uint2 r;
    r.x = (unsigned)__half_as_ushort(h0) | ((unsigned)__half_as_ushort(h1) << 16);
    r.y = (unsigned)__half_as_ushort(l0) | ((unsigned)__half_as_ushort(l1) << 16);
    return r;
}
__device__ __forceinline__ void mma16(float* d, const unsigned* a, const unsigned* b) {
    asm volatile(
        "mma.sync.aligned.m16n8k16.row.col.f32.f16.f16.f32 "
        "{%0,%1,%2,%3}, {%4,%5,%6,%7}, {%8,%9}, {%0,%1,%2,%3};"
        : "+f"(d[0]), "+f"(d[1]), "+f"(d[2]), "+f"(d[3])
        : "r"(a[0]), "r"(a[1]), "r"(a[2]), "r"(a[3]), "r"(b[0]), "r"(b[1]));
}
__device__ __forceinline__ void cpasync16(unsigned dst, const void* src) {
    asm volatile("cp.async.cg.shared.global [%0], [%1], 16;" :: "r"(dst), "l"(src));
}
__device__ __forceinline__ void cpasync_commit() {
    asm volatile("cp.async.commit_group;");
}
template <int N>
__device__ __forceinline__ void cpasync_wait() {
    asm volatile("cp.async.wait_group %0;" :: "n"(N));
}

// ---------------- input reshape ----------------
__global__ void k_reshape(const float* __restrict__ inp) {
    int idx = blockIdx.x * blockDim.x + threadIdx.x;
    if (idx >= ROWS * DD) return;
    int d = idx % DD;
    int r = idx / DD;
    int s = r % SS;
    int b = r / SS;
    g_x[idx] = inp[(size_t)b * (DD * SS) + d * SS + s];
}

// ---------------- weight conversion (per layer) ----------------
__global__ void k_convW(const float* __restrict__ W) {
    int idx = blockIdx.x * blockDim.x + threadIdx.x;
    if (idx >= 4 * KP * DPAD) return;
    int g = idx / (KP * DPAD);
    int rem = idx - g * KP * DPAD;
    int kp = rem / DPAD;
    int e  = rem - kp * DPAD;
    int d0 = kp * 2, d1 = d0 + 1;
    float x0 = (d0 < DD && e < DD) ? W[(size_t)g * DD * DD + (size_t)d0 * DD + e] : 0.f;
    float x1 = (d1 < DD && e < DD) ? W[(size_t)g * DD * DD + (size_t)d1 * DD + e] : 0.f;
    g_W16[idx] = pack_split(x0, x1);
}
__global__ void k_convR(const float* __restrict__ R) {
    int idx = blockIdx.x * blockDim.x + threadIdx.x;
    if (idx >= KP * NCOL) return;
    int kp  = idx / NCOL;
    int col = idx - kp * NCOL;
    int e = col >> 2, g = col & 3;
    int d0 = kp * 2, d1 = d0 + 1;
    float x0 = (d0 < DD) ? R[(size_t)g * DD * DD + (size_t)d0 * DD + e] : 0.f;
    float x1 = (d1 < DD) ? R[(size_t)g * DD * DD + (size_t)d1 * DD + e] : 0.f;
    g_R16[idx] = pack_split(x0, x1);
}

// ---------------- layernorm: emits split/packed h ----------------
__global__ void k_layernorm(const float* __restrict__ lng, const float* __restrict__ lnb) {
    int row = blockIdx.x;
    const float* xr = g_x + (size_t)row * DD;
    __shared__ float red[128];
    __shared__ float s_mu, s_rs;
    float s1 = 0.f, s2 = 0.f;
    for (int d = threadIdx.x; d < DD; d += 128) { float v = xr[d]; s1 += v; s2 += v * v; }
    red[threadIdx.x] = s1; __syncthreads();
    for (int o = 64; o > 0; o >>= 1) { if (threadIdx.x < o) red[threadIdx.x] += red[threadIdx.x + o]; __syncthreads(); }
    if (threadIdx.x == 0) s_mu = red[0] / DD;
    __syncthreads();
    red[threadIdx.x] = s2; __syncthreads();
    for (int o = 64; o > 0; o >>= 1) { if (threadIdx.x < o) red[threadIdx.x] += red[threadIdx.x + o]; __syncthreads(); }
    if (threadIdx.x == 0) {
        float var = red[0] / DD - s_mu * s_mu;
        s_rs = rsqrtf(var + 1e-5f);
    }
    __syncthreads();
    float mu = s_mu, rs = s_rs;
    for (int kp = threadIdx.x; kp < KP; kp += 128) {
        int d0 = kp * 2, d1 = d0 + 1;
        float x0 = (d0 < DD) ? (xr[d0] - mu) * rs * lng[d0] + lnb[d0] : 0.f;
        float x1 = (d1 < DD) ? (xr[d1] - mu) * rs * lng[d1] + lnb[d1] : 0.f;
        g_h16[(size_t)row * KP + kp] = pack_split(x0, x1);
    }
}

// ---------------- W GEMM v2: 128m x 64n, 256 thr, cp.async double-buffered ----------------
#define WA_STRIDE 20
#define WB_STRIDE 68
#define WA_SZ (128 * WA_STRIDE * 8)     /* 20480 per buf */
#define WB_SZ (16 * WB_STRIDE * 8)      /* 8704 per buf  */
#define WG_SMEM (2 * (WA_SZ + WB_SZ))   /* 58368 */

__global__ void __launch_bounds__(256) k_wgemm(const float* __restrict__ bias) {
    extern __shared__ char wsm[];
    uint2* sA = (uint2*)wsm;                          // 2 x [128][20]
    uint2* sB = (uint2*)(wsm + 2 * WA_SZ);            // 2 x [16][68]
    int g  = blockIdx.z;
    int n0 = blockIdx.x * 64;
    int m0 = blockIdx.y * 128;
    int t = threadIdx.x, lane = t & 31, wid = t >> 5;
    int wm = wid >> 1, wn = wid & 1;   // 4 x 2 warp grid

    float acc[2][4][4];
#pragma unroll
    for (int i = 0; i < 2; i++)
#pragma unroll
        for (int j = 0; j < 4; j++)
#pragma unroll
            for (int k = 0; k < 4; k++) acc[i][j][k] = 0.f;

    const uint2* Wbase = g_W16 + (size_t)g * KP * DPAD;
    unsigned sAu = (unsigned)__cvta_generic_to_shared(sA);
    unsigned sBu = (unsigned)__cvta_generic_to_shared(sB);

    int arow = t >> 1, akb = (t & 1) * 8;     // A: 8 uint2 per thread
    int bkp = t >> 4, bcq = (t & 15) * 4;     // B: 4 uint2 per thread

    const uint2* asrc0 = g_h16 + (size_t)(m0 + arow) * KP + akb;
    const uint2* bsrc0 = Wbase + (size_t)bkp * DPAD + n0 + bcq;

    // stage chunk 0 into buf 0
    {
        unsigned da = sAu + (arow * WA_STRIDE + akb) * 8;
#pragma unroll
        for (int j = 0; j < 4; j++) cpasync16(da + j * 16, asrc0 + j * 2);
        unsigned db = sBu + (bkp * WB_STRIDE + bcq) * 8;
#pragma unroll
        for (int j = 0; j < 2; j++) cpasync16(db + j * 16, bsrc0 + j * 2);
        cpasync_commit();
    }

    for (int kc = 0; kc < NKCW; kc++) {
        int buf = kc & 1;
        cpasync_wait<0>();
        __syncthreads();
        if (kc + 1 < NKCW) {    // prefetch next chunk into buf^1
            unsigned da = sAu + ((buf ^ 1) * 128 * WA_STRIDE + arow * WA_STRIDE + akb) * 8;
            const uint2* as = asrc0 + (kc + 1) * 16;
#pragma unroll
            for (int j = 0; j < 4; j++) cpasync16(da + j * 16, as + j * 2);
            unsigned db = sBu + ((buf ^ 1) * 16 * WB_STRIDE + bkp * WB_STRIDE + bcq) * 8;
            const uint2* bs = bsrc0 + (size_t)(kc + 1) * 16 * DPAD;
#pragma unroll
            for (int j = 0; j < 2; j++) cpasync16(db + j * 16, bs + j * 2);
            cpasync_commit();
        }
        const uint2* Ab = sA + buf * (128 * WA_STRIDE);
        const uint2* Bb = sB + buf * (16 * WB_STRIDE);
#pragma unroll
        for (int ts = 0; ts < 2; ts++) {
            int kpf = ts * 8 + (lane & 3);
            unsigned ah[2][4], al[2][4];
#pragma unroll
            for (int mi = 0; mi < 2; mi++) {
                int row = wm * 32 + mi * 16 + (lane >> 2);
                const uint2* Ap = Ab + row * WA_STRIDE;
                uint2 x0 = Ap[kpf],     x1 = Ap[8 * WA_STRIDE + kpf];
                uint2 x2 = Ap[kpf + 4], x3 = Ap[8 * WA_STRIDE + kpf + 4];
                ah[mi][0] = x0.x; ah[mi][1] = x1.x; ah[mi][2] = x2.x; ah[mi][3] = x3.x;
                al[mi][0] = x0.y; al[mi][1] = x1.y; al[mi][2] = x2.y; al[mi][3] = x3.y;
            }
#pragma unroll
            for (int ni = 0; ni < 4; ni++) {
                int cb = wn * 32 + ni * 8 + (lane >> 2);
                uint2 b0 = Bb[kpf * WB_STRIDE + cb];
                uint2 b1 = Bb[(kpf + 4) * WB_STRIDE + cb];
                unsigned bh[2] = {b0.x, b1.x};
                unsigned bl[2] = {b0.y, b1.y};
#pragma unroll
                for (int mi = 0; mi < 2; mi++) {
                    mma16(acc[mi][ni], ah[mi], bh);
                    mma16(acc[mi][ni], ah[mi], bl);
                    mma16(acc[mi][ni], al[mi], bh);
                }
            }
        }
        __syncthreads();
    }
    const float* bp = bias + g * DD;
#pragma unroll
    for (int mi = 0; mi < 2; mi++) {
        int row0 = m0 + wm * 32 + mi * 16 + (lane >> 2);
        int row1 = row0 + 8;
        int b0r = row0 / SS, s0r = row0 - b0r * SS;
        int b1r = row1 / SS, s1r = row1 - b1r * SS;
        float* o0 = g_pre + (size_t)(s0r * BB + b0r) * NCOL + g;
        float* o1 = g_pre + (size_t)(s1r * BB + b1r) * NCOL + g;
#pragma unroll
        for (int ni = 0; ni < 4; ni++) {
            int e = n0 + wn * 32 + ni * 8 + (lane & 3) * 2;
            if (e < DD) {
                float bv0 = bp[e], bv1 = bp[e + 1];
                o0[(e) * 4]     = acc[mi][ni][0] + bv0;
                o0[(e + 1) * 4] = acc[mi][ni][1] + bv1;
                o1[(e) * 4]     = acc[mi][ni][2] + bv0;
                o1[(e + 1) * 4] = acc[mi][ni][3] + bv1;
            }
        }
    }
}

// ---------------- persistent scan (R11 form, restored) ----------------
#define SB_SZ (KP * 68 * 8)            /* 156672: R hi+lo persistent */
#define SA_SZ (2 * 64 * 36 * 8)        /* 36864:  A dbl buffer, 32 kp chunks */
#define SCAN_SMEM (SB_SZ + SA_SZ)      /* 193536 */

__device__ __forceinline__ void group_barrier(int grp, unsigned target) {
    __threadfence();
    __syncthreads();
    if (threadIdx.x == 0) {
        unsigned arr = atomicAdd(&g_bcnt[grp * 32], 1u);
        if (arr == CBLK - 1u) {
            *((volatile unsigned*)&g_bcnt[grp * 32]) = 0u;
            __threadfence();
            atomicExch(&g_bgen[grp * 32], target);
        } else {
            while (*((volatile unsigned*)&g_bgen[grp * 32]) < target) __nanosleep(32);
            __threadfence();
        }
    }
    __syncthreads();
}

__global__ void __launch_bounds__(256, 1) k_scan() {
    extern __shared__ char smraw[];
    uint2* sB = (uint2*)smraw;                 // [kp][c], stride 68
    uint2* sA = (uint2*)(smraw + SB_SZ);       // 2 x [row][kp0..31], stride 36

    int t = threadIdx.x, lane = t & 31;
    int wid = t >> 5, wm = wid >> 2, wn = wid & 3;
    int cb0 = blockIdx.x * 64;
    int b0  = blockIdx.y * 64;
    int grp = blockIdx.y;

    // fill persistent R tile (hi+lo)
    for (int i = t; i < KP * 64; i += 256) {
        int kp = i >> 6, c = i & 63;
        int gc = cb0 + c;
        uint2 v = make_uint2(0u, 0u);
        if (gc < NCOL) v = g_R16[(size_t)kp * NCOL + gc];
        sB[kp * 68 + c] = v;
    }

    // zero h0 (split/packed) for this b-group (redundant across col-blocks; benign)
    for (int i = t; i < 64 * KP; i += 256) g_h16s[0][(size_t)b0 * KP + i] = make_uint2(0u, 0u);

    float sc[2][2][2], snr[2][2][2], smx[2][2][2];
#pragma unroll
    for (int a = 0; a < 2; a++)
#pragma unroll
        for (int b = 0; b < 2; b++)
#pragma unroll
            for (int c = 0; c < 2; c++) { sc[a][b][c] = 0.f; snr[a][b][c] = 0.f; smx[a][b][c] = 0.f; }

    unsigned target = *((volatile unsigned*)&g_bgen[grp * 32]);
    ++target; group_barrier(grp, target);

    const int ar = t >> 2, akpb = (t & 3) * 8;   // A staging: row, kp base (8 uint2 = 4x16B)
    unsigned sAbase = (unsigned)__cvta_generic_to_shared(sA);

    for (int s = 0; s < SS; s++) {
        const uint2* hsrc = g_h16s[s & 1] + (size_t)(b0 + ar) * KP + akpb;
        uint2*       hn16 = g_h16s[(s & 1) ^ 1];

        float acc[2][2][4];
#pragma unroll
        for (int i = 0; i < 2; i++)
#pragma unroll
            for (int j = 0; j < 2; j++)
#pragma unroll
                for (int k = 0; k < 4; k++) acc[i][j][k] = 0.f;

        // stage chunk 0 into buf 0
        {
            unsigned dst = sAbase + (ar * 36 + akpb) * 8;
#pragma unroll
            for (int j = 0; j < 4; j++) cpasync16(dst + j * 16, hsrc + j * 2);
            cpasync_commit();
            cpasync_wait<0>();
        }
        __syncthreads();

        for (int kc = 0; kc < NKC9; kc++) {
            int buf = kc & 1;
            bool more = (kc + 1 < NKC9);
            if (more) {   // stage next chunk into buf^1
                unsigned dst = sAbase + ((buf ^ 1) * (64 * 36) + ar * 36 + akpb) * 8;
                const uint2* src = hsrc + (kc + 1) * 32;
#pragma unroll
                for (int j = 0; j < 4; j++) cpasync16(dst + j * 16, src + j * 2);
                cpasync_commit();
            }
            const uint2* Ab = sA + buf * (64 * 36);
            int kpc = kc * 32;
#pragma unroll
            for (int ts = 0; ts < 4; ts++) {
                int kpl = ts * 8 + (lane & 3);
                unsigned ah[2][4], al[2][4];
#pragma unroll
                for (int mi = 0; mi < 2; mi++) {
                    int row = wm * 32 + mi * 16 + (lane >> 2);
                    const uint2* Ap = Ab + row * 36;
                    uint2 x0 = Ap[kpl],       x1 = Ap[288 + kpl];
                    uint2 x2 = Ap[kpl + 4],   x3 = Ap[288 + kpl + 4];
                    ah[mi][0] = x0.x; ah[mi][1] = x1.x; ah[mi][2] = x2.x; ah[mi][3] = x3.x;
                    al[mi][0] = x0.y; al[mi][1] = x1.y; al[mi][2] = x2.y; al[mi][3] = x3.y;
                }
#pragma unroll
                for (int ni = 0; ni < 2; ni++) {
                    int cb = wn * 16 + ni * 8 + (lane >> 2);
                    int kpf = kpc + kpl;
                    uint2 b0v = sB[kpf * 68 + cb];
                    uint2 b1v = sB[(kpf + 4) * 68 + cb];
                    unsigned bh[2] = {b0v.x, b1v.x};
                    unsigned bl[2] = {b0v.y, b1v.y};
#pragma unroll
                    for (int mi = 0; mi < 2; mi++) {
                        mma16(acc[mi][ni], ah[mi], bh);
                        mma16(acc[mi][ni], ah[mi], bl);
                        mma16(acc[mi][ni], al[mi], bh);
                    }
                }
            }
            if (more) cpasync_wait<0>();
            __syncthreads();
        }

        // fused sLSTM epilogue; h_new written back pre-split/packed
#pragma unroll
        for (int mi = 0; mi < 2; mi++) {
            int br = b0 + wm * 32 + mi * 16 + (lane >> 2);
#pragma unroll
            for (int ni = 0; ni < 2; ni++) {
                float d0 = acc[mi][ni][0], d1 = acc[mi][ni][1];
                float d2 = acc[mi][ni][2], d3 = acc[mi][ni][3];
                float p0 = __shfl_xor_sync(0xffffffffu, d0, 1);
                float p1 = __shfl_xor_sync(0xffffffffu, d1, 1);
                float p2 = __shfl_xor_sync(0xffffffffu, d2, 1);
                float p3 = __shfl_xor_sync(0xffffffffu, d3, 1);
                if ((lane & 1) == 0) {
                    int c = cb0 + wn * 16 + ni * 8 + (lane & 3) * 2;
                    bool valid = (c < NCOL);
                    int e = c >> 2;
                    float hvv[2];
#pragma unroll
                    for (int rr = 0; rr < 2; rr++) {
                        int bb = br + rr * 8;
                        float4 pr = make_float4(0.f, 0.f, 0.f, 0.f);
                        if (valid) pr = *(const float4*)(g_pre + (size_t)(s * BB + bb) * NCOL + c);
                        float it = (rr ? d2 : d0) + pr.x;
                        float ft = (rr ? d3 : d1) + pr.y;
                        float zt = (rr ? p2 : p0) + pr.z;
                        float ot = (rr ? p3 : p1) + pr.w;
                        float mo = smx[mi][ni][rr];
                        float mn = fmaxf(ft + mo, it);
                        float iv = expf(it - mn);
                        float fv = expf(ft + mo - mn);
                        float cn = fv * sc[mi][ni][rr] + iv * tanhf(zt);
                        float nn = fv * snr[mi][ni][rr] + iv;
                        float sg = 1.f / (1.f + expf(-ot));
                        float hv = sg * cn / fmaxf(nn, 1e-6f);
                        sc[mi][ni][rr] = cn; snr[mi][ni][rr] = nn; smx[mi][ni][rr] = mn;
                        hvv[rr] = valid ? hv : 0.f;
                        if (valid) g_x[(size_t)(bb * SS + s) * DD + e] += hv;
                    }
                    // pack (e, e+1) pairs: lane with (lane&3)==0 holds e, partner lane^2 holds e+1
                    float o0 = __shfl_xor_sync(0x55555555u, hvv[0], 2);
                    float o1 = __shfl_xor_sync(0x55555555u, hvv[1], 2);
                    if ((lane & 3) == 0) {
                        int kp = c >> 3;    // e/2, e even on these lanes
                        hn16[(size_t)br * KP + kp]       = pack_split(hvv[0], o0);
                        hn16[(size_t)(br + 8) * KP + kp] = pack_split(hvv[1], o1);
                    }
                }
            }
        }
        ++target; group_barrier(grp, target);
    }
}

// ---------------- batchnorm statistics ----------------
__global__ void k_bnstats() {
    int d = blockIdx.x;
    __shared__ float r1[256], r2[256];
    float s1 = 0.f, s2 = 0.f;
    for (int r = threadIdx.x; r < ROWS; r += 256) {
        float v = g_x[(size_t)r * DD + d];
        s1 += v; s2 += v * v;
    }
    r1[threadIdx.x] = s1; r2[threadIdx.x] = s2; __syncthreads();
    for (int o = 128; o > 0; o >>= 1) {
        if (threadIdx.x < o) { r1[threadIdx.x] += r1[threadIdx.x + o]; r2[threadIdx.x] += r2[threadIdx.x + o]; }
        __syncthreads();
    }
    if (threadIdx.x == 0) {
        float mu = r1[0] / (float)ROWS;
        float var = r2[0] / (float)ROWS - mu * mu;
        g_mean[d] = mu;
        g_rstd[d] = rsqrtf(var + 1e-5f);
    }
}

// ---------------- final projection ----------------
__global__ void k_final(const float* __restrict__ w6, const float* __restrict__ b6,
                        const float* __restrict__ bng, const float* __restrict__ bnb,
                        float* __restrict__ out) {
    int bp = blockIdx.x;
    int b = bp / PP, p = bp % PP;
    __shared__ float r0[128], r1[128];
    float a0 = 0.f, a1 = 0.f;
    for (int i = threadIdx.x; i < OUTIN; i += 128) {
        int flat = p * OUTIN + i;
        int d = flat / SS, s = flat % SS;
        float v = g_x[(size_t)(b * SS + s) * DD + d];
        float xn = (v - g_mean[d]) * g_rstd[d] * bng[d] + bnb[d];
        a0 += xn * w6[i * 2 + 0];
        a1 += xn * w6[i * 2 + 1];
    }
    r0[threadIdx.x] = a0; r1[threadIdx.x] = a1; __syncthreads();
    for (int o = 64; o > 0; o >>= 1) {
        if (threadIdx.x < o) { r0[threadIdx.x] += r0[threadIdx.x + o]; r1[threadIdx.x] += r1[threadIdx.x + o]; }
        __syncthreads();
    }
    if (threadIdx.x == 0) {
        out[bp * 2 + 0] = tanhf(r0[0] + b6[0]);
        out[bp * 2 + 1] = tanhf(r1[0] + b6[1]);
    }
}

// ---------------- launch ----------------
extern "C" void kernel_launch(void* const* d_in, const int* in_sizes, int n_in,
                              void* d_out, int out_size) {
    const float* inp = (const float*)d_in[0];
    const float* Wg  = (const float*)d_in[1];
    const float* Rg  = (const float*)d_in[2];
    const float* bgp = (const float*)d_in[3];
    const float* lng = (const float*)d_in[4];
    const float* lnb = (const float*)d_in[5];
    const float* bng = (const float*)d_in[6];
    const float* bnb = (const float*)d_in[7];
    const float* w6  = (const float*)d_in[8];
    const float* b6  = (const float*)d_in[9];
    float* out = (float*)d_out;

    cudaFuncSetAttribute(k_scan, cudaFuncAttributeMaxDynamicSharedMemorySize, SCAN_SMEM);
    cudaFuncSetAttribute(k_wgemm, cudaFuncAttributeMaxDynamicSharedMemorySize, WG_SMEM);

    const int NWQ = 4 * KP * DPAD;
    k_reshape<<<(ROWS * DD + 255) / 256, 256>>>(inp);
    for (int l = 0; l < NBL; l++) {
        k_convW<<<(NWQ + 255) / 256, 256>>>(Wg + (size_t)l * 4 * DD * DD);
        k_convR<<<(KP * NCOL + 255) / 256, 256>>>(Rg + (size_t)l * 4 * DD * DD);
        k_layernorm<<<ROWS, 128>>>(lng + l * DD, lnb + l * DD);
        k_wgemm<<<dim3(9, 80, 4), 256, WG_SMEM>>>(bgp + (size_t)l * 4 * DD);
        k_scan<<<dim3(CBLK, BBLK), 256, SCAN_SMEM>>>();
    }
    k_bnstats<<<DD, 256>>>();
    k_final<<<BB * PP, 128>>>(w6, b6, bng, bnb, out);
}

// round 15
// speedup vs baseline: 1.5745x; 1.3805x over previous
#include <cuda_runtime.h>
#include <cuda_fp16.h>

#define BB 256
#define DD 564
#define SS 40
#define PP 20
#define NBL 6
#define NCOL 2256      /* 4*DD */
#define ROWS 10240     /* BB*SS */
#define OUTIN 1128
#define KP 288         /* k-pairs (576/2) */
#define NKCW 18        /* wgemm k-chunks of 16 kp */
#define CBLK 36
#define BBLK 4

// ---------------- scratch (static device globals; no allocation) ----------------
__device__ float g_x[ROWS * DD];           // activations (b,s,d)
__device__ float g_pre[SS * BB * NCOL];    // (s,b, e*4+g)  gate-interleaved
__device__ float g_mean[DD];
__device__ float g_rstd[DD];
__device__ unsigned g_bcnt[BBLK * 32];
__device__ unsigned g_bgen[BBLK * 32];
// fp16-split packed operands: uint2 = {hi2 (k,k+1), lo2 (k,k+1)}
__device__ uint2 g_h16[ROWS * KP];         // layernorm out (wgemm A, 3-term)
__device__ uint2 g_W16[4 * KP * DD];       // W  [g][kp][e]
__device__ uint2 g_R16[KP * NCOL];         // R  [kp][e*4+g]
// scan hidden state: single fp16 plane (2-term split), dbl-buffered
__device__ unsigned g_hh[2][BB * KP];

// ---------------- fp16 split helpers ----------------
__device__ __forceinline__ uint2 pack_split(float x0, float x1) {
    __half h0 = __float2half_rn(x0), h1 = __float2half_rn(x1);
    __half l0 = __float2half_rn(x0 - __half2float(h0));
    __half l1 = __float2half_rn(x1 - __half2float(h1));
    uint2 r;
    r.x = (unsigned)__half_as_ushort(h0) | ((unsigned)__half_as_ushort(h1) << 16);
    r.y = (unsigned)__half_as_ushort(l0) | ((unsigned)__half_as_ushort(l1) << 16);
    return r;
}
__device__ __forceinline__ unsigned pack_hi2(float x0, float x1) {
    return (unsigned)__half_as_ushort(__float2half_rn(x0)) |
           ((unsigned)__half_as_ushort(__float2half_rn(x1)) << 16);
}
__device__ __forceinline__ void mma16(float* d, const unsigned* a, const unsigned* b) {
    asm volatile(
        "mma.sync.aligned.m16n8k16.row.col.f32.f16.f16.f32 "
        "{%0,%1,%2,%3}, {%4,%5,%6,%7}, {%8,%9}, {%0,%1,%2,%3};"
        : "+f"(d[0]), "+f"(d[1]), "+f"(d[2]), "+f"(d[3])
        : "r"(a[0]), "r"(a[1]), "r"(a[2]), "r"(a[3]), "r"(b[0]), "r"(b[1]));
}
__device__ __forceinline__ void cpasync16(unsigned dst, const void* src) {
    asm volatile("cp.async.cg.shared.global [%0], [%1], 16;" :: "r"(dst), "l"(src));
}
__device__ __forceinline__ void cpasync_commit() {
    asm volatile("cp.async.commit_group;");
}
template <int N>
__device__ __forceinline__ void cpasync_wait() {
    asm volatile("cp.async.wait_group %0;" :: "n"(N));
}

// ---------------- input reshape ----------------
__global__ void k_reshape(const float* __restrict__ inp) {
    int idx = blockIdx.x * blockDim.x + threadIdx.x;
    if (idx >= ROWS * DD) return;
    int d = idx % DD;
    int r = idx / DD;
    int s = r % SS;
    int b = r / SS;
    g_x[idx] = inp[(size_t)b * (DD * SS) + d * SS + s];
}

// ---------------- weight conversion (per layer) ----------------
__global__ void k_convW(const float* __restrict__ W) {
    int idx = blockIdx.x * blockDim.x + threadIdx.x;
    if (idx >= 4 * KP * DD) return;
    int g = idx / (KP * DD);
    int rem = idx - g * KP * DD;
    int kp = rem / DD;
    int e  = rem - kp * DD;
    int d0 = kp * 2, d1 = d0 + 1;
    float x0 = (d0 < DD) ? W[(size_t)g * DD * DD + (size_t)d0 * DD + e] : 0.f;
    float x1 = (d1 < DD) ? W[(size_t)g * DD * DD + (size_t)d1 * DD + e] : 0.f;
    g_W16[idx] = pack_split(x0, x1);
}
__global__ void k_convR(const float* __restrict__ R) {
    int idx = blockIdx.x * blockDim.x + threadIdx.x;
    if (idx >= KP * NCOL) return;
    int kp  = idx / NCOL;
    int col = idx - kp * NCOL;
    int e = col >> 2, g = col & 3;
    int d0 = kp * 2, d1 = d0 + 1;
    float x0 = (d0 < DD) ? R[(size_t)g * DD * DD + (size_t)d0 * DD + e] : 0.f;
    float x1 = (d1 < DD) ? R[(size_t)g * DD * DD + (size_t)d1 * DD + e] : 0.f;
    g_R16[idx] = pack_split(x0, x1);
}

// ---------------- layernorm: emits split/packed h (for wgemm) ----------------
__global__ void k_layernorm(const float* __restrict__ lng, const float* __restrict__ lnb) {
    int row = blockIdx.x;
    const float* xr = g_x + (size_t)row * DD;
    __shared__ float red[128];
    __shared__ float s_mu, s_rs;
    float s1 = 0.f, s2 = 0.f;
    for (int d = threadIdx.x; d < DD; d += 128) { float v = xr[d]; s1 += v; s2 += v * v; }
    red[threadIdx.x] = s1; __syncthreads();
    for (int o = 64; o > 0; o >>= 1) { if (threadIdx.x < o) red[threadIdx.x] += red[threadIdx.x + o]; __syncthreads(); }
    if (threadIdx.x == 0) s_mu = red[0] / DD;
    __syncthreads();
    red[threadIdx.x] = s2; __syncthreads();
    for (int o = 64; o > 0; o >>= 1) { if (threadIdx.x < o) red[threadIdx.x] += red[threadIdx.x + o]; __syncthreads(); }
    if (threadIdx.x == 0) {
        float var = red[0] / DD - s_mu * s_mu;
        s_rs = rsqrtf(var + 1e-5f);
    }
    __syncthreads();
    float mu = s_mu, rs = s_rs;
    for (int kp = threadIdx.x; kp < KP; kp += 128) {
        int d0 = kp * 2, d1 = d0 + 1;
        float x0 = (d0 < DD) ? (xr[d0] - mu) * rs * lng[d0] + lnb[d0] : 0.f;
        float x1 = (d1 < DD) ? (xr[d1] - mu) * rs * lng[d1] + lnb[d1] : 0.f;
        g_h16[(size_t)row * KP + kp] = pack_split(x0, x1);
    }
}

// ---------------- W GEMM (R11 form, best measured; 3-term split) ----------------
__global__ void __launch_bounds__(128) k_wgemm(const float* __restrict__ bias) {
    __shared__ uint2 sA[64 * 20];
    __shared__ uint2 sB[16 * 68];
    int g  = blockIdx.z;
    int n0 = blockIdx.x * 64;
    int m0 = blockIdx.y * 64;
    int t = threadIdx.x, lane = t & 31, wid = t >> 5;
    int wm = wid >> 1, wn = wid & 1;

    float acc[2][4][4];
#pragma unroll
    for (int i = 0; i < 2; i++)
#pragma unroll
        for (int j = 0; j < 4; j++)
#pragma unroll
            for (int k = 0; k < 4; k++) acc[i][j][k] = 0.f;

    const uint2* Wbase = g_W16 + (size_t)g * KP * DD;

    for (int kc = 0; kc < NKCW; kc++) {
        {
            int row = t >> 1, kb = (t & 1) * 8;
            const uint2* src = g_h16 + (size_t)(m0 + row) * KP + kc * 16 + kb;
            uint2* dst = sA + row * 20 + kb;
            *(uint4*)(dst)     = *(const uint4*)(src);
            *(uint4*)(dst + 2) = *(const uint4*)(src + 2);
            *(uint4*)(dst + 4) = *(const uint4*)(src + 4);
            *(uint4*)(dst + 6) = *(const uint4*)(src + 6);
        }
        {
#pragma unroll
            for (int it = 0; it < 8; it++) {
                int i = t + it * 128;
                int kpr = i >> 6, c = i & 63;
                int ge = n0 + c;
                uint2 v = make_uint2(0u, 0u);
                if (ge < DD) v = Wbase[(size_t)(kc * 16 + kpr) * DD + ge];
                sB[kpr * 68 + c] = v;
            }
        }
        __syncthreads();
#pragma unroll
        for (int ts = 0; ts < 2; ts++) {
            int kpf = ts * 8 + (lane & 3);
            unsigned ah[2][4], al[2][4];
#pragma unroll
            for (int mi = 0; mi < 2; mi++) {
                int row = wm * 32 + mi * 16 + (lane >> 2);
                const uint2* Ap = sA + row * 20;
                uint2 x0 = Ap[kpf], x1 = Ap[160 + kpf];
                uint2 x2 = Ap[kpf + 4], x3 = Ap[160 + kpf + 4];
                ah[mi][0] = x0.x; ah[mi][1] = x1.x; ah[mi][2] = x2.x; ah[mi][3] = x3.x;
                al[mi][0] = x0.y; al[mi][1] = x1.y; al[mi][2] = x2.y; al[mi][3] = x3.y;
            }
#pragma unroll
            for (int ni = 0; ni < 4; ni++) {
                int cb = wn * 32 + ni * 8 + (lane >> 2);
                uint2 b0 = sB[kpf * 68 + cb];
                uint2 b1 = sB[(kpf + 4) * 68 + cb];
                unsigned bh[2] = {b0.x, b1.x};
                unsigned bl[2] = {b0.y, b1.y};
#pragma unroll
                for (int mi = 0; mi < 2; mi++) {
                    mma16(acc[mi][ni], ah[mi], bh);
                    mma16(acc[mi][ni], ah[mi], bl);
                    mma16(acc[mi][ni], al[mi], bh);
                }
            }
        }
        __syncthreads();
    }
    const float* bp = bias + g * DD;
#pragma unroll
    for (int mi = 0; mi < 2; mi++) {
        int row0 = m0 + wm * 32 + mi * 16 + (lane >> 2);
        int row1 = row0 + 8;
        int b0r = row0 / SS, s0r = row0 - b0r * SS;
        int b1r = row1 / SS, s1r = row1 - b1r * SS;
        float* o0 = g_pre + (size_t)(s0r * BB + b0r) * NCOL + g;
        float* o1 = g_pre + (size_t)(s1r * BB + b1r) * NCOL + g;
#pragma unroll
        for (int ni = 0; ni < 4; ni++) {
            int e = n0 + wn * 32 + ni * 8 + (lane & 3) * 2;
            if (e < DD) {
                float bv0 = bp[e], bv1 = bp[e + 1];
                o0[(e) * 4]     = acc[mi][ni][0] + bv0;
                o0[(e + 1) * 4] = acc[mi][ni][1] + bv1;
                o1[(e) * 4]     = acc[mi][ni][2] + bv0;
                o1[(e + 1) * 4] = acc[mi][ni][3] + bv1;
            }
        }
    }
}

// ---------------- persistent scan: 512 thr, 2-term split, single A plane ----------------
#define SB_SZ (KP * 68 * 8)            /* 156672: R hi+lo persistent */
#define SA_SZ (2 * 64 * 36 * 4)        /* 18432:  A (hi only) dbl buffer */
#define SCAN_SMEM (SB_SZ + SA_SZ)      /* 175104 */

__device__ __forceinline__ void group_barrier(int grp, unsigned target) {
    __threadfence();
    __syncthreads();
    if (threadIdx.x == 0) {
        unsigned arr = atomicAdd(&g_bcnt[grp * 32], 1u);
        if (arr == CBLK - 1u) {
            *((volatile unsigned*)&g_bcnt[grp * 32]) = 0u;
            __threadfence();
            atomicExch(&g_bgen[grp * 32], target);
        } else {
            while (*((volatile unsigned*)&g_bgen[grp * 32]) < target) __nanosleep(32);
            __threadfence();
        }
    }
    __syncthreads();
}

__global__ void __launch_bounds__(512, 1) k_scan() {
    extern __shared__ char smraw[];
    uint2* sB = (uint2*)smraw;                      // [kp][c], stride 68
    unsigned* sA = (unsigned*)(smraw + SB_SZ);      // 2 x [row][kp0..31], stride 36

    int t = threadIdx.x, lane = t & 31;
    int wid = t >> 5, wm = wid >> 2, wn = wid & 3;  // 4 x 4 warp grid
    int cb0 = blockIdx.x * 64;
    int b0  = blockIdx.y * 64;
    int grp = blockIdx.y;

    // fill persistent R tile (hi+lo)
    for (int i = t; i < KP * 64; i += 512) {
        int kp = i >> 6, c = i & 63;
        int gc = cb0 + c;
        uint2 v = make_uint2(0u, 0u);
        if (gc < NCOL) v = g_R16[(size_t)kp * NCOL + gc];
        sB[kp * 68 + c] = v;
    }

    // zero h0 plane (redundant across col-blocks; benign)
    for (int i = t; i < 64 * KP; i += 512) g_hh[0][(size_t)b0 * KP + i] = 0u;

    // per-thread sLSTM state (live on even lanes): [ni][rr]
    float scst[2][2], snst[2][2], smst[2][2];
#pragma unroll
    for (int a = 0; a < 2; a++)
#pragma unroll
        for (int b = 0; b < 2; b++) { scst[a][b] = 0.f; snst[a][b] = 0.f; smst[a][b] = 0.f; }

    unsigned target = *((volatile unsigned*)&g_bgen[grp * 32]);
    ++target; group_barrier(grp, target);

    const int arow = t >> 3, aq = (t & 7) * 4;   // staging: 1 x 16B per thread per chunk
    unsigned sAu = (unsigned)__cvta_generic_to_shared(sA);

    for (int s = 0; s < SS; s++) {
        const unsigned* hsrc = g_hh[s & 1] + (size_t)(b0 + arow) * KP + aq;
        unsigned* hnxt = g_hh[(s & 1) ^ 1];

        float acc[2][4];
#pragma unroll
        for (int i = 0; i < 2; i++)
#pragma unroll
            for (int k = 0; k < 4; k++) acc[i][k] = 0.f;

        // stage chunk 0 into buf 0
        cpasync16(sAu + (arow * 36 + aq) * 4, hsrc);
        cpasync_commit();
        cpasync_wait<0>();
        __syncthreads();

        for (int kc = 0; kc < 9; kc++) {
            int buf = kc & 1;
            bool more = (kc + 1 < 9);
            if (more) {
                cpasync16(sAu + ((buf ^ 1) * 2304 + arow * 36 + aq) * 4, hsrc + (kc + 1) * 32);
                cpasync_commit();
            }
            const unsigned* Ab = sA + buf * 2304;
            int row = wm * 16 + (lane >> 2);
#pragma unroll
            for (int ts = 0; ts < 4; ts++) {
                int kpl = ts * 8 + (lane & 3);
                unsigned a[4];
                a[0] = Ab[row * 36 + kpl];       a[1] = Ab[(row + 8) * 36 + kpl];
                a[2] = Ab[row * 36 + kpl + 4];   a[3] = Ab[(row + 8) * 36 + kpl + 4];
                int kpf = kc * 32 + kpl;
#pragma unroll
                for (int ni = 0; ni < 2; ni++) {
                    int cb = wn * 16 + ni * 8 + (lane >> 2);
                    uint2 b0v = sB[kpf * 68 + cb];
                    uint2 b1v = sB[(kpf + 4) * 68 + cb];
                    unsigned bh[2] = {b0v.x, b1v.x};
                    unsigned bl[2] = {b0v.y, b1v.y};
                    mma16(acc[ni], a, bh);
                    mma16(acc[ni], a, bl);
                }
            }
            if (more) cpasync_wait<0>();
            __syncthreads();
        }

        // fused sLSTM epilogue; h_new written back as fp16 hi plane
#pragma unroll
        for (int ni = 0; ni < 2; ni++) {
            float d0 = acc[ni][0], d1 = acc[ni][1];
            float d2 = acc[ni][2], d3 = acc[ni][3];
            float p0 = __shfl_xor_sync(0xffffffffu, d0, 1);
            float p1 = __shfl_xor_sync(0xffffffffu, d1, 1);
            float p2 = __shfl_xor_sync(0xffffffffu, d2, 1);
            float p3 = __shfl_xor_sync(0xffffffffu, d3, 1);
            if ((lane & 1) == 0) {
                int c = cb0 + wn * 16 + ni * 8 + (lane & 3) * 2;
                bool valid = (c < NCOL);
                int e = c >> 2;
                int br = b0 + wm * 16 + (lane >> 2);
                float hvv[2];
#pragma unroll
                for (int rr = 0; rr < 2; rr++) {
                    int bb = br + rr * 8;
                    float4 pr = make_float4(0.f, 0.f, 0.f, 0.f);
                    if (valid) pr = *(const float4*)(g_pre + (size_t)(s * BB + bb) * NCOL + c);
                    float it = (rr ? d2 : d0) + pr.x;
                    float ft = (rr ? d3 : d1) + pr.y;
                    float zt = (rr ? p2 : p0) + pr.z;
                    float ot = (rr ? p3 : p1) + pr.w;
                    float mo = smst[ni][rr];
                    float mn = fmaxf(ft + mo, it);
                    float iv = expf(it - mn);
                    float fv = expf(ft + mo - mn);
                    float cn = fv * scst[ni][rr] + iv * tanhf(zt);
                    float nn = fv * snst[ni][rr] + iv;
                    float sg = 1.f / (1.f + expf(-ot));
                    float hv = sg * cn / fmaxf(nn, 1e-6f);
                    scst[ni][rr] = cn; snst[ni][rr] = nn; smst[ni][rr] = mn;
                    hvv[rr] = valid ? hv : 0.f;
                    if (valid) g_x[(size_t)(bb * SS + s) * DD + e] += hv;
                }
                // pack (e, e+1): lane (lane&3)==0 holds e (even), partner lane^2 holds e+1
                float o0 = __shfl_xor_sync(0x55555555u, hvv[0], 2);
                float o1 = __shfl_xor_sync(0x55555555u, hvv[1], 2);
                if ((lane & 3) == 0) {
                    int kp = e >> 1;
                    hnxt[(size_t)br * KP + kp]       = pack_hi2(hvv[0], o0);
                    hnxt[(size_t)(br + 8) * KP + kp] = pack_hi2(hvv[1], o1);
                }
            }
        }
        ++target; group_barrier(grp, target);
    }
}

// ---------------- batchnorm statistics ----------------
__global__ void k_bnstats() {
    int d = blockIdx.x;
    __shared__ float r1[256], r2[256];
    float s1 = 0.f, s2 = 0.f;
    for (int r = threadIdx.x; r < ROWS; r += 256) {
        float v = g_x[(size_t)r * DD + d];
        s1 += v; s2 += v * v;
    }
    r1[threadIdx.x] = s1; r2[threadIdx.x] = s2; __syncthreads();
    for (int o = 128; o > 0; o >>= 1) {
        if (threadIdx.x < o) { r1[threadIdx.x] += r1[threadIdx.x + o]; r2[threadIdx.x] += r2[threadIdx.x + o]; }
        __syncthreads();
    }
    if (threadIdx.x == 0) {
        float mu = r1[0] / (float)ROWS;
        float var = r2[0] / (float)ROWS - mu * mu;
        g_mean[d] = mu;
        g_rstd[d] = rsqrtf(var + 1e-5f);
    }
}

// ---------------- final projection ----------------
__global__ void k_final(const float* __restrict__ w6, const float* __restrict__ b6,
                        const float* __restrict__ bng, const float* __restrict__ bnb,
                        float* __restrict__ out) {
    int bp = blockIdx.x;
    int b = bp / PP, p = bp % PP;
    __shared__ float r0[128], r1[128];
    float a0 = 0.f, a1 = 0.f;
    for (int i = threadIdx.x; i < OUTIN; i += 128) {
        int flat = p * OUTIN + i;
        int d = flat / SS, s = flat % SS;
        float v = g_x[(size_t)(b * SS + s) * DD + d];
        float xn = (v - g_mean[d]) * g_rstd[d] * bng[d] + bnb[d];
        a0 += xn * w6[i * 2 + 0];
        a1 += xn * w6[i * 2 + 1];
    }
    r0[threadIdx.x] = a0; r1[threadIdx.x] = a1; __syncthreads();
    for (int o = 64; o > 0; o >>= 1) {
        if (threadIdx.x < o) { r0[threadIdx.x] += r0[threadIdx.x + o]; r1[threadIdx.x] += r1[threadIdx.x + o]; }
        __syncthreads();
    }
    if (threadIdx.x == 0) {
        out[bp * 2 + 0] = tanhf(r0[0] + b6[0]);
        out[bp * 2 + 1] = tanhf(r1[0] + b6[1]);
    }
}

// ---------------- launch ----------------
extern "C" void kernel_launch(void* const* d_in, const int* in_sizes, int n_in,
                              void* d_out, int out_size) {
    const float* inp = (const float*)d_in[0];
    const float* Wg  = (const float*)d_in[1];
    const float* Rg  = (const float*)d_in[2];
    const float* bgp = (const float*)d_in[3];
    const float* lng = (const float*)d_in[4];
    const float* lnb = (const float*)d_in[5];
    const float* bng = (const float*)d_in[6];
    const float* bnb = (const float*)d_in[7];
    const float* w6  = (const float*)d_in[8];
    const float* b6  = (const float*)d_in[9];
    float* out = (float*)d_out;

    cudaFuncSetAttribute(k_scan, cudaFuncAttributeMaxDynamicSharedMemorySize, SCAN_SMEM);

    const int NWQ = 4 * KP * DD;
    k_reshape<<<(ROWS * DD + 255) / 256, 256>>>(inp);
    for (int l = 0; l < NBL; l++) {
        k_convW<<<(NWQ + 255) / 256, 256>>>(Wg + (size_t)l * 4 * DD * DD);
        k_convR<<<(KP * NCOL + 255) / 256, 256>>>(Rg + (size_t)l * 4 * DD * DD);
        k_layernorm<<<ROWS, 128>>>(lng + l * DD, lnb + l * DD);
        k_wgemm<<<dim3(9, 160, 4), 128>>>(bgp + (size_t)l * 4 * DD);
        k_scan<<<dim3(CBLK, BBLK), 512, SCAN_SMEM>>>();
    }
    k_bnstats<<<DD, 256>>>();
    k_final<<<BB * PP, 128>>>(w6, b6, bng, bnb, out);
}

// round 16
// speedup vs baseline: 1.8225x; 1.1575x over previous
#include <cuda_runtime.h>
#include <cuda_fp16.h>

#define BB 256
#define DD 564
#define SS 40
#define PP 20
#define NBL 6
#define NCOL 2256      /* 4*DD */
#define ROWS 10240     /* BB*SS */
#define OUTIN 1128
#define KP 288         /* k-pairs (576/2) */
#define NKCW 18        /* wgemm k-chunks of 16 kp */
#define CBLK 36
#define BBLK 4

// ---------------- scratch (static device globals; no allocation) ----------------
__device__ float g_x[ROWS * DD];           // activations (b,s,d)
__device__ float g_pre[SS * BB * NCOL];    // (s,b, e*4+g)  gate-interleaved
__device__ float g_mean[DD];
__device__ float g_rstd[DD];
__device__ unsigned g_bcnt[BBLK * 32];
__device__ unsigned g_bgen[BBLK * 32];
__device__ unsigned g_hh16[ROWS * KP];     // layernorm out, fp16x2 single plane
__device__ uint2 g_W16[4 * KP * DD];       // W  [g][kp][e]  {hi2, lo2}
__device__ uint2 g_R16[KP * NCOL];         // R  [kp][e*4+g] {hi2, lo2}
__device__ unsigned g_hh[2][BB * KP];      // scan hidden state fp16x2, dbl-buffered

// ---------------- fp16 split helpers ----------------
__device__ __forceinline__ uint2 pack_split(float x0, float x1) {
    __half h0 = __float2half_rn(x0), h1 = __float2half_rn(x1);
    __half l0 = __float2half_rn(x0 - __half2float(h0));
    __half l1 = __float2half_rn(x1 - __half2float(h1));
    uint2 r;
    r.x = (unsigned)__half_as_ushort(h0) | ((unsigned)__half_as_ushort(h1) << 16);
    r.y = (unsigned)__half_as_ushort(l0) | ((unsigned)__half_as_ushort(l1) << 16);
    return r;
}
__device__ __forceinline__ unsigned pack_hi2(float x0, float x1) {
    return (unsigned)__half_as_ushort(__float2half_rn(x0)) |
           ((unsigned)__half_as_ushort(__float2half_rn(x1)) << 16);
}
__device__ __forceinline__ void mma16(float* d, const unsigned* a, const unsigned* b) {
    asm volatile(
        "mma.sync.aligned.m16n8k16.row.col.f32.f16.f16.f32 "
        "{%0,%1,%2,%3}, {%4,%5,%6,%7}, {%8,%9}, {%0,%1,%2,%3};"
        : "+f"(d[0]), "+f"(d[1]), "+f"(d[2]), "+f"(d[3])
        : "r"(a[0]), "r"(a[1]), "r"(a[2]), "r"(a[3]), "r"(b[0]), "r"(b[1]));
}
__device__ __forceinline__ void cpasync16(unsigned dst, const void* src) {
    asm volatile("cp.async.cg.shared.global [%0], [%1], 16;" :: "r"(dst), "l"(src));
}
__device__ __forceinline__ void cpasync_commit() {
    asm volatile("cp.async.commit_group;");
}
template <int N>
__device__ __forceinline__ void cpasync_wait() {
    asm volatile("cp.async.wait_group %0;" :: "n"(N));
}

// ---------------- input reshape ----------------
__global__ void k_reshape(const float* __restrict__ inp) {
    int idx = blockIdx.x * blockDim.x + threadIdx.x;
    if (idx >= ROWS * DD) return;
    int d = idx % DD;
    int r = idx / DD;
    int s = r % SS;
    int b = r / SS;
    g_x[idx] = inp[(size_t)b * (DD * SS) + d * SS + s];
}

// ---------------- weight conversion (per layer) ----------------
__global__ void k_convW(const float* __restrict__ W) {
    int idx = blockIdx.x * blockDim.x + threadIdx.x;
    if (idx >= 4 * KP * DD) return;
    int g = idx / (KP * DD);
    int rem = idx - g * KP * DD;
    int kp = rem / DD;
    int e  = rem - kp * DD;
    int d0 = kp * 2, d1 = d0 + 1;
    float x0 = (d0 < DD) ? W[(size_t)g * DD * DD + (size_t)d0 * DD + e] : 0.f;
    float x1 = (d1 < DD) ? W[(size_t)g * DD * DD + (size_t)d1 * DD + e] : 0.f;
    g_W16[idx] = pack_split(x0, x1);
}
__global__ void k_convR(const float* __restrict__ R) {
    int idx = blockIdx.x * blockDim.x + threadIdx.x;
    if (idx >= KP * NCOL) return;
    int kp  = idx / NCOL;
    int col = idx - kp * NCOL;
    int e = col >> 2, g = col & 3;
    int d0 = kp * 2, d1 = d0 + 1;
    float x0 = (d0 < DD) ? R[(size_t)g * DD * DD + (size_t)d0 * DD + e] : 0.f;
    float x1 = (d1 < DD) ? R[(size_t)g * DD * DD + (size_t)d1 * DD + e] : 0.f;
    g_R16[idx] = pack_split(x0, x1);
}

// ---------------- layernorm: emits fp16 single-plane h ----------------
__global__ void k_layernorm(const float* __restrict__ lng, const float* __restrict__ lnb) {
    int row = blockIdx.x;
    const float* xr = g_x + (size_t)row * DD;
    __shared__ float red[128];
    __shared__ float s_mu, s_rs;
    float s1 = 0.f, s2 = 0.f;
    for (int d = threadIdx.x; d < DD; d += 128) { float v = xr[d]; s1 += v; s2 += v * v; }
    red[threadIdx.x] = s1; __syncthreads();
    for (int o = 64; o > 0; o >>= 1) { if (threadIdx.x < o) red[threadIdx.x] += red[threadIdx.x + o]; __syncthreads(); }
    if (threadIdx.x == 0) s_mu = red[0] / DD;
    __syncthreads();
    red[threadIdx.x] = s2; __syncthreads();
    for (int o = 64; o > 0; o >>= 1) { if (threadIdx.x < o) red[threadIdx.x] += red[threadIdx.x + o]; __syncthreads(); }
    if (threadIdx.x == 0) {
        float var = red[0] / DD - s_mu * s_mu;
        s_rs = rsqrtf(var + 1e-5f);
    }
    __syncthreads();
    float mu = s_mu, rs = s_rs;
    for (int kp = threadIdx.x; kp < KP; kp += 128) {
        int d0 = kp * 2, d1 = d0 + 1;
        float x0 = (d0 < DD) ? (xr[d0] - mu) * rs * lng[d0] + lnb[d0] : 0.f;
        float x1 = (d1 < DD) ? (xr[d1] - mu) * rs * lng[d1] + lnb[d1] : 0.f;
        g_hh16[(size_t)row * KP + kp] = pack_hi2(x0, x1);
    }
}

// ---------------- W GEMM: 2-term split (A fp16, W hi+lo) ----------------
__global__ void __launch_bounds__(128) k_wgemm(const float* __restrict__ bias) {
    __shared__ unsigned sA[64 * 20];   // [row][kp0..15], stride 20
    __shared__ uint2 sB[16 * 68];      // [kp][e0..63],   stride 68
    int g  = blockIdx.z;
    int n0 = blockIdx.x * 64;
    int m0 = blockIdx.y * 64;
    int t = threadIdx.x, lane = t & 31, wid = t >> 5;
    int wm = wid >> 1, wn = wid & 1;

    float acc[2][4][4];
#pragma unroll
    for (int i = 0; i < 2; i++)
#pragma unroll
        for (int j = 0; j < 4; j++)
#pragma unroll
            for (int k = 0; k < 4; k++) acc[i][j][k] = 0.f;

    const uint2* Wbase = g_W16 + (size_t)g * KP * DD;

    for (int kc = 0; kc < NKCW; kc++) {
        {   // A: 64 rows x 16 kp fp16x2; 8 uints per thread
            int row = t >> 1, kb = (t & 1) * 8;
            const unsigned* src = g_hh16 + (size_t)(m0 + row) * KP + kc * 16 + kb;
            unsigned* dst = sA + row * 20 + kb;
            *(uint4*)(dst)     = *(const uint4*)(src);
            *(uint4*)(dst + 4) = *(const uint4*)(src + 4);
        }
        {
#pragma unroll
            for (int it = 0; it < 8; it++) {
                int i = t + it * 128;
                int kpr = i >> 6, c = i & 63;
                int ge = n0 + c;
                uint2 v = make_uint2(0u, 0u);
                if (ge < DD) v = Wbase[(size_t)(kc * 16 + kpr) * DD + ge];
                sB[kpr * 68 + c] = v;
            }
        }
        __syncthreads();
#pragma unroll
        for (int ts = 0; ts < 2; ts++) {
            int kpf = ts * 8 + (lane & 3);
            unsigned a[2][4];
#pragma unroll
            for (int mi = 0; mi < 2; mi++) {
                int row = wm * 32 + mi * 16 + (lane >> 2);
                const unsigned* Ap = sA + row * 20;
                a[mi][0] = Ap[kpf];       a[mi][1] = Ap[160 + kpf];
                a[mi][2] = Ap[kpf + 4];   a[mi][3] = Ap[160 + kpf + 4];
            }
#pragma unroll
            for (int ni = 0; ni < 4; ni++) {
                int cb = wn * 32 + ni * 8 + (lane >> 2);
                uint2 b0 = sB[kpf * 68 + cb];
                uint2 b1 = sB[(kpf + 4) * 68 + cb];
                unsigned bh[2] = {b0.x, b1.x};
                unsigned bl[2] = {b0.y, b1.y};
#pragma unroll
                for (int mi = 0; mi < 2; mi++) {
                    mma16(acc[mi][ni], a[mi], bh);
                    mma16(acc[mi][ni], a[mi], bl);
                }
            }
        }
        __syncthreads();
    }
    const float* bp = bias + g * DD;
#pragma unroll
    for (int mi = 0; mi < 2; mi++) {
        int row0 = m0 + wm * 32 + mi * 16 + (lane >> 2);
        int row1 = row0 + 8;
        int b0r = row0 / SS, s0r = row0 - b0r * SS;
        int b1r = row1 / SS, s1r = row1 - b1r * SS;
        float* o0 = g_pre + (size_t)(s0r * BB + b0r) * NCOL + g;
        float* o1 = g_pre + (size_t)(s1r * BB + b1r) * NCOL + g;
#pragma unroll
        for (int ni = 0; ni < 4; ni++) {
            int e = n0 + wn * 32 + ni * 8 + (lane & 3) * 2;
            if (e < DD) {
                float bv0 = bp[e], bv1 = bp[e + 1];
                o0[(e) * 4]     = acc[mi][ni][0] + bv0;
                o0[(e + 1) * 4] = acc[mi][ni][1] + bv1;
                o1[(e) * 4]     = acc[mi][ni][2] + bv0;
                o1[(e + 1) * 4] = acc[mi][ni][3] + bv1;
            }
        }
    }
}

// ---------------- persistent scan: 512 thr, 2-term, 3 chunks of 96 kp ----------------
#define SB_SZ (KP * 68 * 8)            /* 156672: R hi+lo persistent */
#define SA_STR 100                     /* uint stride (==4 mod 8) */
#define SA_BUF (64 * SA_STR)           /* 6400 uints per buffer */
#define SA_SZ (2 * SA_BUF * 4)         /* 51200 */
#define SCAN_SMEM (SB_SZ + SA_SZ)      /* 207872 */
#define NCH 3
#define CHKP 96

__device__ __forceinline__ void group_barrier(int grp, unsigned target) {
    __threadfence();
    __syncthreads();
    if (threadIdx.x == 0) {
        unsigned arr = atomicAdd(&g_bcnt[grp * 32], 1u);
        if (arr == CBLK - 1u) {
            *((volatile unsigned*)&g_bcnt[grp * 32]) = 0u;
            __threadfence();
            atomicExch(&g_bgen[grp * 32], target);
        } else {
            while (*((volatile unsigned*)&g_bgen[grp * 32]) < target) __nanosleep(32);
            __threadfence();
        }
    }
    __syncthreads();
}

__global__ void __launch_bounds__(512, 1) k_scan() {
    extern __shared__ char smraw[];
    uint2* sB = (uint2*)smraw;                      // [kp][c], stride 68
    unsigned* sA = (unsigned*)(smraw + SB_SZ);      // 2 x [row][kp0..95], stride 100

    int t = threadIdx.x, lane = t & 31;
    int wid = t >> 5, wm = wid >> 2, wn = wid & 3;  // 4 x 4 warp grid
    int cb0 = blockIdx.x * 64;
    int b0  = blockIdx.y * 64;
    int grp = blockIdx.y;

    // fill persistent R tile (hi+lo)
    for (int i = t; i < KP * 64; i += 512) {
        int kp = i >> 6, c = i & 63;
        int gc = cb0 + c;
        uint2 v = make_uint2(0u, 0u);
        if (gc < NCOL) v = g_R16[(size_t)kp * NCOL + gc];
        sB[kp * 68 + c] = v;
    }

    // zero h0 plane (redundant across col-blocks; benign)
    for (int i = t; i < 64 * KP; i += 512) g_hh[0][(size_t)b0 * KP + i] = 0u;

    // per-thread sLSTM state (live on even lanes): [ni][rr]
    float scst[2][2], snst[2][2], smst[2][2];
#pragma unroll
    for (int a = 0; a < 2; a++)
#pragma unroll
        for (int b = 0; b < 2; b++) { scst[a][b] = 0.f; snst[a][b] = 0.f; smst[a][b] = 0.f; }

    unsigned target = *((volatile unsigned*)&g_bgen[grp * 32]);
    ++target; group_barrier(grp, target);

    // staging: 64 rows x 96 uints per chunk; 12 uints (3x16B) per thread
    const int arow = t >> 3, abase = (t & 7) * 12;
    unsigned sAu = (unsigned)__cvta_generic_to_shared(sA);

    for (int s = 0; s < SS; s++) {
        const unsigned* hsrc = g_hh[s & 1] + (size_t)(b0 + arow) * KP + abase;
        unsigned* hnxt = g_hh[(s & 1) ^ 1];

        float acc[2][4];
#pragma unroll
        for (int i = 0; i < 2; i++)
#pragma unroll
            for (int k = 0; k < 4; k++) acc[i][k] = 0.f;

        // stage chunk 0 into buf 0
        {
            unsigned dst = sAu + (arow * SA_STR + abase) * 4;
#pragma unroll
            for (int j = 0; j < 3; j++) cpasync16(dst + j * 16, hsrc + j * 4);
            cpasync_commit();
            cpasync_wait<0>();
        }
        __syncthreads();

        for (int kc = 0; kc < NCH; kc++) {
            int buf = kc & 1;
            bool more = (kc + 1 < NCH);
            if (more) {
                unsigned dst = sAu + ((buf ^ 1) * SA_BUF + arow * SA_STR + abase) * 4;
                const unsigned* src = hsrc + (kc + 1) * CHKP;
#pragma unroll
                for (int j = 0; j < 3; j++) cpasync16(dst + j * 16, src + j * 4);
                cpasync_commit();
            }
            const unsigned* Ab = sA + buf * SA_BUF;
            int row = wm * 16 + (lane >> 2);
            const unsigned* Ap = Ab + row * SA_STR;
#pragma unroll
            for (int ts = 0; ts < 12; ts++) {
                int kpl = ts * 8 + (lane & 3);
                unsigned a[4];
                a[0] = Ap[kpl];                  a[1] = Ap[8 * SA_STR + kpl];
                a[2] = Ap[kpl + 4];              a[3] = Ap[8 * SA_STR + kpl + 4];
                int kpf = kc * CHKP + kpl;
#pragma unroll
                for (int ni = 0; ni < 2; ni++) {
                    int cb = wn * 16 + ni * 8 + (lane >> 2);
                    uint2 b0v = sB[kpf * 68 + cb];
                    uint2 b1v = sB[(kpf + 4) * 68 + cb];
                    unsigned bh[2] = {b0v.x, b1v.x};
                    unsigned bl[2] = {b0v.y, b1v.y};
                    mma16(acc[ni], a, bh);
                    mma16(acc[ni], a, bl);
                }
            }
            if (more) cpasync_wait<0>();
            __syncthreads();
        }

        // fused sLSTM epilogue; h_new written back as fp16x2 plane
#pragma unroll
        for (int ni = 0; ni < 2; ni++) {
            float d0 = acc[ni][0], d1 = acc[ni][1];
            float d2 = acc[ni][2], d3 = acc[ni][3];
            float p0 = __shfl_xor_sync(0xffffffffu, d0, 1);
            float p1 = __shfl_xor_sync(0xffffffffu, d1, 1);
            float p2 = __shfl_xor_sync(0xffffffffu, d2, 1);
            float p3 = __shfl_xor_sync(0xffffffffu, d3, 1);
            if ((lane & 1) == 0) {
                int c = cb0 + wn * 16 + ni * 8 + (lane & 3) * 2;
                bool valid = (c < NCOL);
                int e = c >> 2;
                int br = b0 + wm * 16 + (lane >> 2);
                float hvv[2];
#pragma unroll
                for (int rr = 0; rr < 2; rr++) {
                    int bb = br + rr * 8;
                    float4 pr = make_float4(0.f, 0.f, 0.f, 0.f);
                    if (valid) pr = *(const float4*)(g_pre + (size_t)(s * BB + bb) * NCOL + c);
                    float it = (rr ? d2 : d0) + pr.x;
                    float ft = (rr ? d3 : d1) + pr.y;
                    float zt = (rr ? p2 : p0) + pr.z;
                    float ot = (rr ? p3 : p1) + pr.w;
                    float mo = smst[ni][rr];
                    float mn = fmaxf(ft + mo, it);
                    float iv = expf(it - mn);
                    float fv = expf(ft + mo - mn);
                    float cn = fv * scst[ni][rr] + iv * tanhf(zt);
                    float nn = fv * snst[ni][rr] + iv;
                    float sg = 1.f / (1.f + expf(-ot));
                    float hv = sg * cn / fmaxf(nn, 1e-6f);
                    scst[ni][rr] = cn; snst[ni][rr] = nn; smst[ni][rr] = mn;
                    hvv[rr] = valid ? hv : 0.f;
                    if (valid) g_x[(size_t)(bb * SS + s) * DD + e] += hv;
                }
                // pack (e, e+1): lane (lane&3)==0 holds e (even), partner lane^2 holds e+1
                float o0 = __shfl_xor_sync(0x55555555u, hvv[0], 2);
                float o1 = __shfl_xor_sync(0x55555555u, hvv[1], 2);
                if ((lane & 3) == 0) {
                    int kp = e >> 1;
                    hnxt[(size_t)br * KP + kp]       = pack_hi2(hvv[0], o0);
                    hnxt[(size_t)(br + 8) * KP + kp] = pack_hi2(hvv[1], o1);
                }
            }
        }
        ++target; group_barrier(grp, target);
    }
}

// ---------------- batchnorm statistics ----------------
__global__ void k_bnstats() {
    int d = blockIdx.x;
    __shared__ float r1[256], r2[256];
    float s1 = 0.f, s2 = 0.f;
    for (int r = threadIdx.x; r < ROWS; r += 256) {
        float v = g_x[(size_t)r * DD + d];
        s1 += v; s2 += v * v;
    }
    r1[threadIdx.x] = s1; r2[threadIdx.x] = s2; __syncthreads();
    for (int o = 128; o > 0; o >>= 1) {
        if (threadIdx.x < o) { r1[threadIdx.x] += r1[threadIdx.x + o]; r2[threadIdx.x] += r2[threadIdx.x + o]; }
        __syncthreads();
    }
    if (threadIdx.x == 0) {
        float mu = r1[0] / (float)ROWS;
        float var = r2[0] / (float)ROWS - mu * mu;
        g_mean[d] = mu;
        g_rstd[d] = rsqrtf(var + 1e-5f);
    }
}

// ---------------- final projection ----------------
__global__ void k_final(const float* __restrict__ w6, const float* __restrict__ b6,
                        const float* __restrict__ bng, const float* __restrict__ bnb,
                        float* __restrict__ out) {
    int bp = blockIdx.x;
    int b = bp / PP, p = bp % PP;
    __shared__ float r0[128], r1[128];
    float a0 = 0.f, a1 = 0.f;
    for (int i = threadIdx.x; i < OUTIN; i += 128) {
        int flat = p * OUTIN + i;
        int d = flat / SS, s = flat % SS;
        float v = g_x[(size_t)(b * SS + s) * DD + d];
        float xn = (v - g_mean[d]) * g_rstd[d] * bng[d] + bnb[d];
        a0 += xn * w6[i * 2 + 0];
        a1 += xn * w6[i * 2 + 1];
    }
    r0[threadIdx.x] = a0; r1[threadIdx.x] = a1; __syncthreads();
    for (int o = 64; o > 0; o >>= 1) {
        if (threadIdx.x < o) { r0[threadIdx.x] += r0[threadIdx.x + o]; r1[threadIdx.x] += r1[threadIdx.x + o]; }
        __syncthreads();
    }
    if (threadIdx.x == 0) {
        out[bp * 2 + 0] = tanhf(r0[0] + b6[0]);
        out[bp * 2 + 1] = tanhf(r1[0] + b6[1]);
    }
}

// ---------------- launch ----------------
extern "C" void kernel_launch(void* const* d_in, const int* in_sizes, int n_in,
                              void* d_out, int out_size) {
    const float* inp = (const float*)d_in[0];
    const float* Wg  = (const float*)d_in[1];
    const float* Rg  = (const float*)d_in[2];
    const float* bgp = (const float*)d_in[3];
    const float* lng = (const float*)d_in[4];
    const float* lnb = (const float*)d_in[5];
    const float* bng = (const float*)d_in[6];
    const float* bnb = (const float*)d_in[7];
    const float* w6  = (const float*)d_in[8];
    const float* b6  = (const float*)d_in[9];
    float* out = (float*)d_out;

    cudaFuncSetAttribute(k_scan, cudaFuncAttributeMaxDynamicSharedMemorySize, SCAN_SMEM);

    const int NWQ = 4 * KP * DD;
    k_reshape<<<(ROWS * DD + 255) / 256, 256>>>(inp);
    for (int l = 0; l < NBL; l++) {
        k_convW<<<(NWQ + 255) / 256, 256>>>(Wg + (size_t)l * 4 * DD * DD);
        k_convR<<<(KP * NCOL + 255) / 256, 256>>>(Rg + (size_t)l * 4 * DD * DD);
        k_layernorm<<<ROWS, 128>>>(lng + l * DD, lnb + l * DD);
        k_wgemm<<<dim3(9, 160, 4), 128>>>(bgp + (size_t)l * 4 * DD);
        k_scan<<<dim3(CBLK, BBLK), 512, SCAN_SMEM>>>();
    }
    k_bnstats<<<DD, 256>>>();
    k_final<<<BB * PP, 128>>>(w6, b6, bng, bnb, out);
}